// round 15
// baseline (speedup 1.0000x reference)
#include <cuda_runtime.h>

#define BATCH 256
#define NPTS  4096
#define DYN_SMEM (2*(NPTS*16 + NPTS*4))
#define FULLM 0xffffffffu

// group barrier: id g+1, 256 threads
#define GBAR(g) asm volatile("bar.sync %0, 256;" :: "r"((g)+1) : "memory")

// ---------- fast double helpers: fp32 seed + 1 Newton step ----------
__device__ __forceinline__ double drecip(double x) {
  double y = (double)__fdividef(1.0f, (float)x);
  y = y * (2.0 - x * y);
  return y;
}
__device__ __forceinline__ double drsqrt(double x) {
  double y = (double)rsqrtf((float)x);
  y = y * (1.5 - 0.5 * x * y * y);
  return y;
}

__device__ __forceinline__ void inv3x3(const float* __restrict__ Km, float* __restrict__ out) {
  double a=Km[0], b=Km[1], c=Km[2], d=Km[3], e=Km[4], f=Km[5], g=Km[6], h=Km[7], i=Km[8];
  double det = a*(e*i - f*h) - b*(d*i - f*g) + c*(d*h - e*g);
  double inv = 1.0 / det;
  out[0]=(float)((e*i - f*h)*inv); out[1]=(float)((c*h - b*i)*inv); out[2]=(float)((b*f - c*e)*inv);
  out[3]=(float)((f*g - d*i)*inv); out[4]=(float)((a*i - c*g)*inv); out[5]=(float)((c*d - a*f)*inv);
  out[6]=(float)((d*h - e*g)*inv); out[7]=(float)((b*g - a*h)*inv); out[8]=(float)((a*e - b*d)*inv);
}

__device__ __forceinline__ int p2i(int a, int b) {
  int mn = a < b ? a : b, mx = a < b ? b : a;
  return mn*(5-mn)/2 + mx;
}

template<int P, int Q>
__device__ __forceinline__ void rot3f(float g[3][3], float Qm[3][3]) {
  constexpr int K2 = 3 - P - Q;
  float apq = g[P][Q];
  float app = g[P][P], aqq = g[Q][Q];
  if (fabsf(apq) <= 1e-12f * (fabsf(app) + fabsf(aqq))) return;
  float tau = __fdividef(aqq - app, 2.0f * apq);
  float tt = ((tau >= 0.0f) ? 1.0f : -1.0f) / (fabsf(tau) + sqrtf(1.0f + tau*tau));
  float c = rsqrtf(1.0f + tt*tt);
  float s = tt * c;
  float akp = g[K2][P], akq = g[K2][Q];
  float np = c*akp - s*akq, nq = s*akp + c*akq;
  g[K2][P] = np; g[P][K2] = np;
  g[K2][Q] = nq; g[Q][K2] = nq;
  g[P][P] = app - tt*apq;
  g[Q][Q] = aqq + tt*apq;
  g[P][Q] = 0.0f; g[Q][P] = 0.0f;
  #pragma unroll
  for (int r = 0; r < 3; r++) {
    float qp = Qm[r][P], qq = Qm[r][Q];
    Qm[r][P] = c*qp - s*qq;
    Qm[r][Q] = s*qp + c*qq;
  }
}

// ---------- fused kernel: 512 threads, 2 batches/block, warp-group per batch ----------
__global__ __launch_bounds__(512, 1) void k_fused(const float* __restrict__ kpts0,
                                                  const float* __restrict__ kpts1,
                                                  const float* __restrict__ conf,
                                                  const float* __restrict__ tscale,
                                                  const float* __restrict__ Kmat,
                                                  float* __restrict__ out) {
  const int tid = threadIdx.x;
  const int g = tid >> 8;             // group 0/1 -> batch
  const int gtid = tid & 255;
  const int gwarp = (tid >> 5) & 7;   // warp within group
  const int lane = tid & 31;
  const int bb = blockIdx.x*2 + g;

  extern __shared__ char dyn[];
  float4* sP = (float4*)(dyn + (size_t)g*NPTS*16);
  float*  sW = (float*)(dyn + 2*NPTS*16 + (size_t)g*NPTS*4);

  __shared__ float sKi[2][18];
  __shared__ float sred[2][8][36];
  __shared__ double sd[2][81];
  __shared__ float sT[2][36];
  __shared__ float sR1[2][9], st3[2][3];
  __shared__ float scs[2][4], sss[2][4];
  __shared__ double sDinv[2][9], sSigma[2], sxd[2][9];
  __shared__ float sUVf[2][18], sSgnF[2];
  __shared__ int sIpiv[2][9];
  __shared__ int sPerm[2][9];
  __shared__ int sAffine[2];

  // ---- phase 0: K inverses for both batches ----
  if (tid < 2) {
    int bq = blockIdx.x*2 + tid;
    float ki0[9], ki1[9];
    inv3x3(Kmat + bq*18, ki0);
    inv3x3(Kmat + bq*18 + 9, ki1);
    #pragma unroll
    for (int i=0;i<9;i++) { sKi[tid][i]=ki0[i]; sKi[tid][9+i]=ki1[i]; }
    sAffine[tid] = (ki0[6]==0.f && ki0[7]==0.f && ki0[8]==1.f &&
                    ki1[6]==0.f && ki1[7]==0.f && ki1[8]==1.f) ? 1 : 0;
  }
  __syncthreads();

  float Ki0[9], Ki1[9];
  #pragma unroll
  for (int i=0;i<9;i++){ Ki0[i]=sKi[g][i]; Ki1[i]=sKi[g][9+i]; }
  const int affine = sAffine[g];

  const float2* kp0 = (const float2*)(kpts0) + (size_t)bb*NPTS;
  const float2* kp1 = (const float2*)(kpts1) + (size_t)bb*NPTS;
  const float*  wv  = conf + (size_t)bb*NPTS;

  // ---- phase 1: accumulate T[6][6] + stage coords (group-concurrent) ----
  {
    float acc[36];
    #pragma unroll
    for (int i=0;i<36;i++) acc[i]=0.f;

    float2 b0[4], b1[4]; float bwv[4];
    #pragma unroll
    for (int i=0;i<4;i++) {
      b0[i] = kp0[gtid + i*256];
      b1[i] = kp1[gtid + i*256];
      bwv[i] = wv[gtid + i*256];
    }
    #pragma unroll
    for (int k = 0; k < NPTS/256; k++) {
      float2 c0 = b0[k & 3], c1 = b1[k & 3];
      float  cw = bwv[k & 3];
      if (k + 4 < NPTS/256) {
        b0[k & 3] = kp0[gtid + (k+4)*256];
        b1[k & 3] = kp1[gtid + (k+4)*256];
        bwv[k & 3] = wv[gtid + (k+4)*256];
      }
      float x00 = Ki0[0]*c0.x + Ki0[1]*c0.y + Ki0[2];
      float x01 = Ki0[3]*c0.x + Ki0[4]*c0.y + Ki0[5];
      float x02 = Ki0[6]*c0.x + Ki0[7]*c0.y + Ki0[8];
      float x10 = Ki1[0]*c1.x + Ki1[1]*c1.y + Ki1[2];
      float x11 = Ki1[3]*c1.x + Ki1[4]*c1.y + Ki1[5];
      float x12 = Ki1[6]*c1.x + Ki1[7]*c1.y + Ki1[8];
      int n = gtid + k*256;
      sP[n] = make_float4(x00, x01, x10, x11);
      sW[n] = cw;
      float s0a[6] = {x00*x00, x00*x01, x00*x02, x01*x01, x01*x02, x02*x02};
      float s1a[6] = {x10*x10, x10*x11, x10*x12, x11*x11, x11*x12, x12*x12};
      float ws1[6];
      #pragma unroll
      for (int a=0;a<6;a++) ws1[a] = cw*s1a[a];
      #pragma unroll
      for (int a=0;a<6;a++)
        #pragma unroll
        for (int bq=0;bq<6;bq++)
          acc[a*6+bq] = fmaf(ws1[a], s0a[bq], acc[a*6+bq]);
    }
    #pragma unroll
    for (int i=0;i<36;i++) {
      acc[i] += __shfl_down_sync(FULLM, acc[i], 16);
      acc[i] += __shfl_down_sync(FULLM, acc[i], 8);
      acc[i] += __shfl_down_sync(FULLM, acc[i], 4);
      acc[i] += __shfl_down_sync(FULLM, acc[i], 2);
      acc[i] += __shfl_down_sync(FULLM, acc[i], 1);
    }
    if (lane == 0) {
      #pragma unroll
      for (int i=0;i<36;i++) sred[g][gwarp][i] = acc[i];
    }
    GBAR(g);
    if (gtid < 36) {
      float v = 0.f;
      #pragma unroll
      for (int wp=0; wp<8; wp++) v += sred[g][wp][gtid];
      sT[g][gtid] = v;
    }
    GBAR(g);
  }

  // ---- phase 2: eigensolve on warp 0 of each group (concurrent) ----
  if (gwarp == 0) {
    const int s = g;
    float* A = (float*)&sd[s][0];

    if (lane < 9) {
      const int i0 = lane / 3, j0 = lane % 3;
      #pragma unroll
      for (int j = 0; j < 9; j++)
        A[lane*9+j] = sT[s][p2i(i0, j/3)*6 + p2i(j0, j%3)];
    }
    __syncwarp();

    for (int sweep = 0; sweep < 3; sweep++) {
      for (int r = 0; r < 9; r++) {
        const int bye = (5 * ((2*r) % 9)) % 9;
        if (lane < 4) {
          int d = lane + 1;
          int a = (bye + d) % 9;
          int bq = (bye + 9 - d) % 9;
          int p = a < bq ? a : bq;
          int q = a < bq ? bq : a;
          float apq = A[p*9+q], app = A[p*9+p], aqq = A[q*9+q];
          float c = 1.0f, sv = 0.0f;
          if (fabsf(apq) > 6e-8f * (fabsf(app) + fabsf(aqq))) {
            float tau = __fdividef(aqq - app, 2.0f * apq);
            float t = ((tau >= 0.0f) ? 1.0f : -1.0f) / (fabsf(tau) + sqrtf(1.0f + tau*tau));
            c = rsqrtf(1.0f + t*t);
            sv = t * c;
          }
          scs[s][lane] = c; sss[s][lane] = sv;
        }
        __syncwarp();
        float cr[4], sr[4];
        int pr[4], qr[4];
        #pragma unroll
        for (int d = 0; d < 4; d++) {
          cr[d] = scs[s][d]; sr[d] = sss[s][d];
          int a = (bye + d + 1) % 9;
          int bq = (bye + 8 - d) % 9;
          pr[d] = a < bq ? a : bq;
          qr[d] = a < bq ? bq : a;
        }
        if (lane < 9) {
          #pragma unroll
          for (int d = 0; d < 4; d++) {
            int p = pr[d], q = qr[d];
            float vp = A[lane*9+p], vq = A[lane*9+q];
            A[lane*9+p] = cr[d]*vp - sr[d]*vq;
            A[lane*9+q] = sr[d]*vp + cr[d]*vq;
          }
        }
        __syncwarp();
        if (lane < 9) {
          #pragma unroll
          for (int d = 0; d < 4; d++) {
            int p = pr[d], q = qr[d];
            float vp = A[p*9+lane], vq = A[q*9+lane];
            A[p*9+lane] = cr[d]*vp - sr[d]*vq;
            A[q*9+lane] = sr[d]*vp + cr[d]*vq;
          }
        }
        __syncwarp();
      }
    }

    if (lane == 0) {
      float mv = A[0];
      #pragma unroll
      for (int k=1;k<9;k++) mv = fminf(mv, A[k*9+k]);
      sSigma[s] = (double)mv;
    }
    __syncwarp();
    double sigma = sSigma[s];

    double* D = &sd[s][0];
    if (lane < 9) {
      int i0 = lane/3, j0 = lane%3;
      #pragma unroll
      for (int j=0;j<9;j++)
        D[lane*9+j] = (double)sT[s][p2i(i0, j/3)*6 + p2i(j0, j%3)];
      D[lane*9+lane] -= sigma;
    }
    __syncwarp();

    for (int k=0;k<9;k++) {
      double av = (lane < 9 && lane >= k) ? fabs(D[lane*9+k]) : -1.0;
      int ai = lane;
      #pragma unroll
      for (int off=16; off; off>>=1) {
        double ov = __shfl_xor_sync(FULLM, av, off);
        int oi = __shfl_xor_sync(FULLM, ai, off);
        if (ov > av || (ov == av && oi < ai)) { av = ov; ai = oi; }
      }
      int p = ai;
      if (lane == 0) sIpiv[s][k] = p;
      if (p != k && lane < 9) {
        double t = D[k*9+lane]; D[k*9+lane] = D[p*9+lane]; D[p*9+lane] = t;
      }
      __syncwarp();
      double pv = D[k*9+k];
      if (fabs(pv) < 1e-30) pv = (pv >= 0.0) ? 1e-30 : -1e-30;
      double ipv = drecip(pv);
      if (lane == 0) sDinv[s][k] = ipv;
      if (lane > k && lane < 9) {
        double l = D[lane*9+k] * ipv;
        D[lane*9+k] = l;
        for (int j=k+1;j<9;j++) D[lane*9+j] -= l * D[k*9+j];
      }
      __syncwarp();
    }

    if (lane == 0) {
      int idx[9];
      #pragma unroll
      for (int i=0;i<9;i++) idx[i]=i;
      for (int k=0;k<9;k++){ int p=sIpiv[s][k]; int t=idx[k]; idx[k]=idx[p]; idx[p]=t; }
      #pragma unroll
      for (int i=0;i<9;i++) sPerm[s][i]=idx[i];
    }
    __syncwarp();

    double row[9]; double dinv_l = 1.0; int permL = 0;
    if (lane < 9) {
      #pragma unroll
      for (int j=0;j<9;j++) row[j] = D[lane*9+j];
      dinv_l = sDinv[s][lane];
      permL = sPerm[s][lane];
    }

    double rv = 1.0;
    for (int it=0; it<2; it++) {
      if (lane < 9) sxd[s][lane] = rv;
      __syncwarp();
      if (lane < 9) rv = sxd[s][permL];
      __syncwarp();
      #pragma unroll
      for (int j=0;j<8;j++) {
        double yj = __shfl_sync(FULLM, rv, j);
        if (lane > j && lane < 9) rv -= row[j]*yj;
      }
      #pragma unroll
      for (int j=8;j>=0;j--) {
        if (lane == j) rv *= dinv_l;
        double xj = __shfl_sync(FULLM, rv, j);
        if (lane < j) rv -= row[j]*xj;
      }
      double c2 = (lane < 9) ? rv*rv : 0.0;
      #pragma unroll
      for (int off=16; off; off>>=1) c2 += __shfl_xor_sync(FULLM, c2, off);
      rv *= drsqrt(c2);
    }
    if (lane < 9) sxd[s][lane] = rv;
    __syncwarp();

    if (lane == 0) {
      float e[9];
      #pragma unroll
      for (int k=0;k<9;k++) e[k] = (float)sxd[s][k];

      float G3[3][3];
      #pragma unroll
      for (int i=0;i<3;i++)
        #pragma unroll
        for (int j=0;j<3;j++)
          G3[i][j] = e[0+i]*e[0+j] + e[3+i]*e[3+j] + e[6+i]*e[6+j];

      float Qm[3][3] = {{1.f,0.f,0.f},{0.f,1.f,0.f},{0.f,0.f,1.f}};
      #pragma unroll
      for (int sw=0; sw<4; sw++) { rot3f<0,1>(G3,Qm); rot3f<0,2>(G3,Qm); rot3f<1,2>(G3,Qm); }

      float lam0=G3[0][0], lam1=G3[1][1], lam2=G3[2][2];
      int o0, o1, o2;
      if (lam0 >= lam1) {
        if (lam0 >= lam2) { o0=0; if (lam1>=lam2){o1=1;o2=2;} else {o1=2;o2=1;} }
        else              { o0=2; o1=0; o2=1; }
      } else {
        if (lam1 >= lam2) { o0=1; if (lam0>=lam2){o1=0;o2=2;} else {o1=2;o2=0;} }
        else              { o0=2; o1=1; o2=0; }
      }
      float v1[3] = {Qm[0][o0], Qm[1][o0], Qm[2][o0]};
      float v2[3] = {Qm[0][o1], Qm[1][o1], Qm[2][o1]};
      float v3[3] = {Qm[0][o2], Qm[1][o2], Qm[2][o2]};

      float u1[3], u2[3], u3[3];
      #pragma unroll
      for (int i=0;i<3;i++) {
        u1[i] = e[3*i+0]*v1[0] + e[3*i+1]*v1[1] + e[3*i+2]*v1[2];
        u2[i] = e[3*i+0]*v2[0] + e[3*i+1]*v2[1] + e[3*i+2]*v2[2];
      }
      float in1 = rsqrtf(fmaxf(u1[0]*u1[0]+u1[1]*u1[1]+u1[2]*u1[2], 1e-30f));
      float in2 = rsqrtf(fmaxf(u2[0]*u2[0]+u2[1]*u2[1]+u2[2]*u2[2], 1e-30f));
      #pragma unroll
      for (int i=0;i<3;i++){ u1[i]*=in1; u2[i]*=in2; }
      u3[0] = u1[1]*u2[2] - u1[2]*u2[1];
      u3[1] = u1[2]*u2[0] - u1[0]*u2[2];
      u3[2] = u1[0]*u2[1] - u1[1]*u2[0];
      float in3 = rsqrtf(fmaxf(u3[0]*u3[0]+u3[1]*u3[1]+u3[2]*u3[2], 1e-30f));
      #pragma unroll
      for (int i=0;i<3;i++) u3[i]*=in3;

      float detU = u1[0]*(u2[1]*u3[2]-u2[2]*u3[1])
                 - u1[1]*(u2[0]*u3[2]-u2[2]*u3[0])
                 + u1[2]*(u2[0]*u3[1]-u2[1]*u3[0]);
      float detV = v1[0]*(v2[1]*v3[2]-v2[2]*v3[1])
                 - v1[1]*(v2[0]*v3[2]-v2[2]*v3[0])
                 + v1[2]*(v2[0]*v3[1]-v2[1]*v3[0]);
      float dd = detU * detV;
      sSgnF[s] = (dd > 0.0f) ? 1.0f : ((dd < 0.0f) ? -1.0f : 0.0f);
      #pragma unroll
      for (int i=0;i<3;i++) {
        sUVf[s][i]    = u1[i];
        sUVf[s][3+i]  = u2[i];
        sUVf[s][6+i]  = u3[i];
        sUVf[s][9+i]  = v1[i];
        sUVf[s][12+i] = v2[i];
        sUVf[s][15+i] = v3[i];
        st3[s][i] = u3[i];
      }
    }
    __syncwarp();

    if (lane < 9) {
      int i = lane / 3, j = lane % 3;
      float u1i = sUVf[s][i], u2i = sUVf[s][3+i], u3i = sUVf[s][6+i];
      float v1j = sUVf[s][9+j], v2j = sUVf[s][12+j], v3j = sUVf[s][15+j];
      sR1[s][lane] = ( u2i*v1j - u1i*v2j + u3i*v3j)*sSgnF[s];
    }
  }
  GBAR(g);

  // ---- phase 3: cheirality (group-concurrent; H-trick for candidate 2) ----
  float R1[9];
  #pragma unroll
  for (int i=0;i<9;i++) R1[i]=sR1[g][i];
  const float tv0=st3[g][0], tv1=st3[g][1], tv2=st3[g][2];

  float sc0=0.f, sc1=0.f, sc2=0.f, sc3=0.f;
  if (affine) {
    #pragma unroll
    for (int k = 0; k < NPTS/256; k++) {
      int n = gtid + k*256;
      float4 q = sP[n];
      float w = sW[n];
      float bbv = q.z*q.z + q.w*q.w + 1.0f;
      float bt = q.z*tv0 + q.w*tv1 + tv2;
      float a0 = R1[0]*q.x + R1[1]*q.y + R1[2];
      float a1 = R1[3]*q.x + R1[4]*q.y + R1[5];
      float a2 = R1[6]*q.x + R1[7]*q.y + R1[8];
      float aa = a0*a0 + a1*a1 + a2*a2;
      float ab = a0*q.z + a1*q.w + a2;
      float at = a0*tv0 + a1*tv1 + a2*tv2;
      {
        float det = aa*bbv - ab*ab + 1e-9f;
        float n0 = -at*bbv + ab*bt;
        float n1 = aa*bt - ab*at;
        bool dpn = det >= 0.f;
        if (dpn ? (n0 > 0.f && n1 > 0.f) : (n0 < 0.f && n1 < 0.f)) sc0 += w;
        if (dpn ? (n0 < 0.f && n1 < 0.f) : (n0 > 0.f && n1 > 0.f)) sc1 += w;
      }
      {
        float ab2 = 2.0f*at*bt - ab;
        float det = aa*bbv - ab2*ab2 + 1e-9f;
        float n0 = -at*bbv + ab2*bt;
        float n1 = aa*bt - ab2*at;
        bool dpn = det >= 0.f;
        if (dpn ? (n0 > 0.f && n1 > 0.f) : (n0 < 0.f && n1 < 0.f)) sc2 += w;
        if (dpn ? (n0 < 0.f && n1 < 0.f) : (n0 > 0.f && n1 > 0.f)) sc3 += w;
      }
    }
  } else {
    #pragma unroll
    for (int k = 0; k < NPTS/256; k++) {
      int n = gtid + k*256;
      float2 p0 = kp0[n]; float2 p1 = kp1[n]; float w = wv[n];
      float x00 = Ki0[0]*p0.x + Ki0[1]*p0.y + Ki0[2];
      float x01 = Ki0[3]*p0.x + Ki0[4]*p0.y + Ki0[5];
      float x02 = Ki0[6]*p0.x + Ki0[7]*p0.y + Ki0[8];
      float x10 = Ki1[0]*p1.x + Ki1[1]*p1.y + Ki1[2];
      float x11 = Ki1[3]*p1.x + Ki1[4]*p1.y + Ki1[5];
      float x12 = Ki1[6]*p1.x + Ki1[7]*p1.y + Ki1[8];
      float bbv = x10*x10 + x11*x11 + x12*x12;
      float bt = x10*tv0 + x11*tv1 + x12*tv2;
      float a0 = R1[0]*x00 + R1[1]*x01 + R1[2]*x02;
      float a1 = R1[3]*x00 + R1[4]*x01 + R1[5]*x02;
      float a2 = R1[6]*x00 + R1[7]*x01 + R1[8]*x02;
      float aa = a0*a0 + a1*a1 + a2*a2;
      float ab = a0*x10 + a1*x11 + a2*x12;
      float at = a0*tv0 + a1*tv1 + a2*tv2;
      {
        float det = aa*bbv - ab*ab + 1e-9f;
        float n0 = -at*bbv + ab*bt;
        float n1 = aa*bt - ab*at;
        bool dpn = det >= 0.f;
        if (dpn ? (n0 > 0.f && n1 > 0.f) : (n0 < 0.f && n1 < 0.f)) sc0 += w;
        if (dpn ? (n0 < 0.f && n1 < 0.f) : (n0 > 0.f && n1 > 0.f)) sc1 += w;
      }
      {
        float ab2 = 2.0f*at*bt - ab;
        float det = aa*bbv - ab2*ab2 + 1e-9f;
        float n0 = -at*bbv + ab2*bt;
        float n1 = aa*bt - ab2*at;
        bool dpn = det >= 0.f;
        if (dpn ? (n0 > 0.f && n1 > 0.f) : (n0 < 0.f && n1 < 0.f)) sc2 += w;
        if (dpn ? (n0 < 0.f && n1 < 0.f) : (n0 > 0.f && n1 > 0.f)) sc3 += w;
      }
    }
  }
  #pragma unroll
  for (int off=16; off; off>>=1) {
    sc0 += __shfl_down_sync(FULLM, sc0, off);
    sc1 += __shfl_down_sync(FULLM, sc1, off);
    sc2 += __shfl_down_sync(FULLM, sc2, off);
    sc3 += __shfl_down_sync(FULLM, sc3, off);
  }
  if (lane == 0) { sred[g][gwarp][0]=sc0; sred[g][gwarp][1]=sc1; sred[g][gwarp][2]=sc2; sred[g][gwarp][3]=sc3; }
  GBAR(g);
  if (gtid == 0) {
    float s0=0.f, s1=0.f, s2=0.f, s3=0.f;
    #pragma unroll
    for (int wp=0; wp<8; wp++){ s0+=sred[g][wp][0]; s1+=sred[g][wp][1]; s2+=sred[g][wp][2]; s3+=sred[g][wp][3]; }
    float bs = s0; int bi = 0;
    if (s1 > bs){ bs=s1; bi=1; }
    if (s2 > bs){ bs=s2; bi=2; }
    if (s3 > bs){ bs=s3; bi=3; }
    float Rsel[9];
    if (bi < 2) {
      #pragma unroll
      for (int i=0;i<9;i++) Rsel[i] = sR1[g][i];
    } else {
      float t3a[3] = {st3[g][0], st3[g][1], st3[g][2]};
      #pragma unroll
      for (int i=0;i<3;i++) {
        #pragma unroll
        for (int j=0;j<3;j++) {
          float dotc = t3a[0]*sR1[g][0*3+j] + t3a[1]*sR1[g][1*3+j] + t3a[2]*sR1[g][2*3+j];
          Rsel[i*3+j] = 2.0f*t3a[i]*dotc - sR1[g][i*3+j];
        }
      }
    }
    float sgn = (bi & 1) ? -1.f : 1.f;
    float ts = tscale[bb*2];
    float t0 = (sgn*st3[g][0])*ts;
    float t1 = (sgn*st3[g][1])*ts;
    float t2 = (sgn*st3[g][2])*ts;
    float* o = out + (size_t)bb*32;
    o[0]=Rsel[0]; o[1]=Rsel[1]; o[2]=Rsel[2];  o[3]=t0;
    o[4]=Rsel[3]; o[5]=Rsel[4]; o[6]=Rsel[5];  o[7]=t1;
    o[8]=Rsel[6]; o[9]=Rsel[7]; o[10]=Rsel[8]; o[11]=t2;
    o[12]=0.f; o[13]=0.f; o[14]=0.f; o[15]=1.f;
    float ti0 = -(Rsel[0]*t0 + Rsel[3]*t1 + Rsel[6]*t2);
    float ti1 = -(Rsel[1]*t0 + Rsel[4]*t1 + Rsel[7]*t2);
    float ti2 = -(Rsel[2]*t0 + Rsel[5]*t1 + Rsel[8]*t2);
    o[16]=Rsel[0]; o[17]=Rsel[3]; o[18]=Rsel[6]; o[19]=ti0;
    o[20]=Rsel[1]; o[21]=Rsel[4]; o[22]=Rsel[7]; o[23]=ti1;
    o[24]=Rsel[2]; o[25]=Rsel[5]; o[26]=Rsel[8]; o[27]=ti2;
    o[28]=0.f; o[29]=0.f; o[30]=0.f; o[31]=1.f;
  }
}

extern "C" void kernel_launch(void* const* d_in, const int* in_sizes, int n_in,
                              void* d_out, int out_size) {
  const float* kpts0  = (const float*)d_in[0];
  const float* kpts1  = (const float*)d_in[1];
  const float* conf   = (const float*)d_in[2];
  const float* tscale = (const float*)d_in[3];
  const float* Kmat   = (const float*)d_in[4];
  float* out = (float*)d_out;

  cudaFuncSetAttribute(k_fused, cudaFuncAttributeMaxDynamicSharedMemorySize, DYN_SMEM);
  k_fused<<<BATCH/2, 512, DYN_SMEM>>>(kpts0, kpts1, conf, tscale, Kmat, out);
}

// round 16
// speedup vs baseline: 1.1172x; 1.1172x over previous
#include <cuda_runtime.h>

#define BATCH 256
#define NPTS  4096
#define DYN_SMEM (2*(NPTS*16 + NPTS*4))
#define FULLM 0xffffffffu

typedef unsigned long long f32x2;
__device__ __forceinline__ f32x2 pk2(float a, float b){ f32x2 r; asm("mov.b64 %0, {%1, %2};" : "=l"(r) : "f"(a), "f"(b)); return r; }
__device__ __forceinline__ void upk2(f32x2 v, float& a, float& b){ asm("mov.b64 {%0, %1}, %2;" : "=f"(a), "=f"(b) : "l"(v)); }
__device__ __forceinline__ f32x2 ffma2(f32x2 a, f32x2 b, f32x2 c){ f32x2 r; asm("fma.rn.f32x2 %0, %1, %2, %3;" : "=l"(r) : "l"(a), "l"(b), "l"(c)); return r; }
__device__ __forceinline__ f32x2 fmul2(f32x2 a, f32x2 b){ f32x2 r; asm("mul.rn.f32x2 %0, %1, %2;" : "=l"(r) : "l"(a), "l"(b)); return r; }

// ---------- fast double helpers ----------
__device__ __forceinline__ double drecip(double x) {
  double y = (double)__fdividef(1.0f, (float)x);
  y = y * (2.0 - x * y);
  return y;
}
__device__ __forceinline__ double drsqrt(double x) {
  double y = (double)rsqrtf((float)x);
  y = y * (1.5 - 0.5 * x * y * y);
  return y;
}

__device__ __forceinline__ void inv3x3(const float* __restrict__ Km, float* __restrict__ out) {
  double a=Km[0], b=Km[1], c=Km[2], d=Km[3], e=Km[4], f=Km[5], g=Km[6], h=Km[7], i=Km[8];
  double det = a*(e*i - f*h) - b*(d*i - f*g) + c*(d*h - e*g);
  double inv = 1.0 / det;
  out[0]=(float)((e*i - f*h)*inv); out[1]=(float)((c*h - b*i)*inv); out[2]=(float)((b*f - c*e)*inv);
  out[3]=(float)((f*g - d*i)*inv); out[4]=(float)((a*i - c*g)*inv); out[5]=(float)((c*d - a*f)*inv);
  out[6]=(float)((d*h - e*g)*inv); out[7]=(float)((b*g - a*h)*inv); out[8]=(float)((a*e - b*d)*inv);
}

__device__ __forceinline__ int p2i(int a, int b) {
  int mn = a < b ? a : b, mx = a < b ? b : a;
  return mn*(5-mn)/2 + mx;
}

template<int P, int Q>
__device__ __forceinline__ void rot3f(float g[3][3], float Qm[3][3]) {
  constexpr int K2 = 3 - P - Q;
  float apq = g[P][Q];
  float app = g[P][P], aqq = g[Q][Q];
  if (fabsf(apq) <= 1e-12f * (fabsf(app) + fabsf(aqq))) return;
  float tau = __fdividef(aqq - app, 2.0f * apq);
  float tt = ((tau >= 0.0f) ? 1.0f : -1.0f) / (fabsf(tau) + sqrtf(1.0f + tau*tau));
  float c = rsqrtf(1.0f + tt*tt);
  float s = tt * c;
  float akp = g[K2][P], akq = g[K2][Q];
  float np = c*akp - s*akq, nq = s*akp + c*akq;
  g[K2][P] = np; g[P][K2] = np;
  g[K2][Q] = nq; g[Q][K2] = nq;
  g[P][P] = app - tt*apq;
  g[Q][Q] = aqq + tt*apq;
  g[P][Q] = 0.0f; g[Q][P] = 0.0f;
  #pragma unroll
  for (int r = 0; r < 3; r++) {
    float qp = Qm[r][P], qq = Qm[r][Q];
    Qm[r][P] = c*qp - s*qq;
    Qm[r][Q] = s*qp + c*qq;
  }
}

// ---------- fused kernel: one block per TWO batches (R14 structure) ----------
__global__ __launch_bounds__(256, 1) void k_fused(const float* __restrict__ kpts0,
                                                  const float* __restrict__ kpts1,
                                                  const float* __restrict__ conf,
                                                  const float* __restrict__ tscale,
                                                  const float* __restrict__ Kmat,
                                                  float* __restrict__ out) {
  const int tid = threadIdx.x;
  const int warp = tid >> 5, lane = tid & 31;

  extern __shared__ char dyn[];
  float4* sPv0 = (float4*)dyn;
  float4* sPv1 = (float4*)(dyn + NPTS*16);
  float*  sWv0 = (float*)(dyn + 2*NPTS*16);
  float*  sWv1 = (float*)(dyn + 2*NPTS*16 + NPTS*4);

  __shared__ float sKi[2][18];
  __shared__ float sred[8][36];
  __shared__ double sd[2][81];
  __shared__ float sT[2][36];
  __shared__ float sR1[2][9], st3[2][3];
  __shared__ float scs[2][4], sss[2][4];
  __shared__ double sDinv[2][9], sSigma[2], sxd[2][9];
  __shared__ float sUVf[2][18], sSgnF[2];
  __shared__ int sIpiv[2][9];
  __shared__ int sPerm[2][9];
  __shared__ int sAffine[2];

  // ---- phase 0: K inverses ----
  if (tid < 2) {
    int bb = blockIdx.x*2 + tid;
    float ki0[9], ki1[9];
    inv3x3(Kmat + bb*18, ki0);
    inv3x3(Kmat + bb*18 + 9, ki1);
    #pragma unroll
    for (int i=0;i<9;i++) { sKi[tid][i]=ki0[i]; sKi[tid][9+i]=ki1[i]; }
    sAffine[tid] = (ki0[6]==0.f && ki0[7]==0.f && ki0[8]==1.f &&
                    ki1[6]==0.f && ki1[7]==0.f && ki1[8]==1.f) ? 1 : 0;
  }
  __syncthreads();

  // ---- phase 1: packed f32x2 accumulation of T[6][6], 2 points/iter ----
  for (int s = 0; s < 2; s++) {
    const int bb = blockIdx.x*2 + s;
    f32x2 K0p[9], K1p[9];
    #pragma unroll
    for (int i=0;i<9;i++){
      K0p[i] = pk2(sKi[s][i],   sKi[s][i]);
      K1p[i] = pk2(sKi[s][9+i], sKi[s][9+i]);
    }
    const float4* kp0v = (const float4*)kpts0 + (size_t)bb*(NPTS/2);
    const float4* kp1v = (const float4*)kpts1 + (size_t)bb*(NPTS/2);
    const float2* wv2  = (const float2*)conf  + (size_t)bb*(NPTS/2);
    float4* sP = s ? sPv1 : sPv0;
    float2* sW2 = (float2*)(s ? sWv1 : sWv0);

    f32x2 acc[36];
    #pragma unroll
    for (int i=0;i<36;i++) acc[i] = 0ULL;

    float4 b0[4], b1[4]; float2 bw[4];
    #pragma unroll
    for (int i=0;i<4;i++) {
      b0[i] = kp0v[tid + i*256];
      b1[i] = kp1v[tid + i*256];
      bw[i] = wv2[tid + i*256];
    }
    #pragma unroll
    for (int k = 0; k < NPTS/512; k++) {   // 8 iterations, 2 points each
      float4 c0 = b0[k & 3], c1 = b1[k & 3];
      float2 cw = bw[k & 3];
      if (k + 4 < NPTS/512) {
        b0[k & 3] = kp0v[tid + (k+4)*256];
        b1[k & 3] = kp1v[tid + (k+4)*256];
        bw[k & 3] = wv2[tid + (k+4)*256];
      }
      f32x2 px = pk2(c0.x, c0.z), py = pk2(c0.y, c0.w);
      f32x2 qx = pk2(c1.x, c1.z), qy = pk2(c1.y, c1.w);
      f32x2 x00p = ffma2(K0p[0], px, ffma2(K0p[1], py, K0p[2]));
      f32x2 x01p = ffma2(K0p[3], px, ffma2(K0p[4], py, K0p[5]));
      f32x2 x02p = ffma2(K0p[6], px, ffma2(K0p[7], py, K0p[8]));
      f32x2 x10p = ffma2(K1p[0], qx, ffma2(K1p[1], qy, K1p[2]));
      f32x2 x11p = ffma2(K1p[3], qx, ffma2(K1p[4], qy, K1p[5]));
      f32x2 x12p = ffma2(K1p[6], qx, ffma2(K1p[7], qy, K1p[8]));

      // stage normalized coords (same layout as before: sP[n] = point n)
      int n2 = tid + k*256;
      {
        float a00,b00,a01,b01,a10,b10,a11,b11;
        upk2(x00p,a00,b00); upk2(x01p,a01,b01);
        upk2(x10p,a10,b10); upk2(x11p,a11,b11);
        sP[2*n2]   = make_float4(a00,a01,a10,a11);
        sP[2*n2+1] = make_float4(b00,b01,b10,b11);
        sW2[n2] = cw;
      }

      f32x2 s0p[6] = {fmul2(x00p,x00p), fmul2(x00p,x01p), fmul2(x00p,x02p),
                      fmul2(x01p,x01p), fmul2(x01p,x02p), fmul2(x02p,x02p)};
      f32x2 s1p[6] = {fmul2(x10p,x10p), fmul2(x10p,x11p), fmul2(x10p,x12p),
                      fmul2(x11p,x11p), fmul2(x11p,x12p), fmul2(x12p,x12p)};
      f32x2 wp = pk2(cw.x, cw.y);
      f32x2 ws[6];
      #pragma unroll
      for (int a=0;a<6;a++) ws[a] = fmul2(wp, s1p[a]);
      #pragma unroll
      for (int a=0;a<6;a++)
        #pragma unroll
        for (int bq=0;bq<6;bq++)
          acc[a*6+bq] = ffma2(ws[a], s0p[bq], acc[a*6+bq]);
    }
    float accs[36];
    #pragma unroll
    for (int i=0;i<36;i++){ float lo,hi; upk2(acc[i],lo,hi); accs[i]=lo+hi; }
    #pragma unroll
    for (int i=0;i<36;i++) {
      accs[i] += __shfl_down_sync(FULLM, accs[i], 16);
      accs[i] += __shfl_down_sync(FULLM, accs[i], 8);
      accs[i] += __shfl_down_sync(FULLM, accs[i], 4);
      accs[i] += __shfl_down_sync(FULLM, accs[i], 2);
      accs[i] += __shfl_down_sync(FULLM, accs[i], 1);
    }
    if (lane == 0) {
      #pragma unroll
      for (int i=0;i<36;i++) sred[warp][i] = accs[i];
    }
    __syncthreads();
    if (tid < 36) {
      float v = 0.f;
      #pragma unroll
      for (int wp2=0; wp2<8; wp2++) v += sred[wp2][tid];
      sT[s][tid] = v;
    }
    __syncthreads();
  }

  // ---- phase 2: TWO concurrent eigensolves (warp 0 / warp 1) ----
  if (warp < 2) {
    const int s = warp;
    float* A = (float*)&sd[s][0];

    if (lane < 9) {
      const int i0 = lane / 3, j0 = lane % 3;
      #pragma unroll
      for (int j = 0; j < 9; j++)
        A[lane*9+j] = sT[s][p2i(i0, j/3)*6 + p2i(j0, j%3)];
    }
    __syncwarp();

    for (int sweep = 0; sweep < 3; sweep++) {
      for (int r = 0; r < 9; r++) {
        const int bye = (5 * ((2*r) % 9)) % 9;
        if (lane < 4) {
          int d = lane + 1;
          int a = (bye + d) % 9;
          int bq = (bye + 9 - d) % 9;
          int p = a < bq ? a : bq;
          int q = a < bq ? bq : a;
          float apq = A[p*9+q], app = A[p*9+p], aqq = A[q*9+q];
          float c = 1.0f, sv = 0.0f;
          if (fabsf(apq) > 6e-8f * (fabsf(app) + fabsf(aqq))) {
            float tau = __fdividef(aqq - app, 2.0f * apq);
            float t = ((tau >= 0.0f) ? 1.0f : -1.0f) / (fabsf(tau) + sqrtf(1.0f + tau*tau));
            c = rsqrtf(1.0f + t*t);
            sv = t * c;
          }
          scs[s][lane] = c; sss[s][lane] = sv;
        }
        __syncwarp();
        float cr[4], sr[4];
        int pr[4], qr[4];
        #pragma unroll
        for (int d = 0; d < 4; d++) {
          cr[d] = scs[s][d]; sr[d] = sss[s][d];
          int a = (bye + d + 1) % 9;
          int bq = (bye + 8 - d) % 9;
          pr[d] = a < bq ? a : bq;
          qr[d] = a < bq ? bq : a;
        }
        if (lane < 9) {
          #pragma unroll
          for (int d = 0; d < 4; d++) {
            int p = pr[d], q = qr[d];
            float vp = A[lane*9+p], vq = A[lane*9+q];
            A[lane*9+p] = cr[d]*vp - sr[d]*vq;
            A[lane*9+q] = sr[d]*vp + cr[d]*vq;
          }
        }
        __syncwarp();
        if (lane < 9) {
          #pragma unroll
          for (int d = 0; d < 4; d++) {
            int p = pr[d], q = qr[d];
            float vp = A[p*9+lane], vq = A[q*9+lane];
            A[p*9+lane] = cr[d]*vp - sr[d]*vq;
            A[q*9+lane] = sr[d]*vp + cr[d]*vq;
          }
        }
        __syncwarp();
      }
    }

    if (lane == 0) {
      float mv = A[0];
      #pragma unroll
      for (int k=1;k<9;k++) mv = fminf(mv, A[k*9+k]);
      sSigma[s] = (double)mv;
    }
    __syncwarp();
    double sigma = sSigma[s];

    double* D = &sd[s][0];
    if (lane < 9) {
      int i0 = lane/3, j0 = lane%3;
      #pragma unroll
      for (int j=0;j<9;j++)
        D[lane*9+j] = (double)sT[s][p2i(i0, j/3)*6 + p2i(j0, j%3)];
      D[lane*9+lane] -= sigma;
    }
    __syncwarp();

    for (int k=0;k<9;k++) {
      double av = (lane < 9 && lane >= k) ? fabs(D[lane*9+k]) : -1.0;
      int ai = lane;
      #pragma unroll
      for (int off=16; off; off>>=1) {
        double ov = __shfl_xor_sync(FULLM, av, off);
        int oi = __shfl_xor_sync(FULLM, ai, off);
        if (ov > av || (ov == av && oi < ai)) { av = ov; ai = oi; }
      }
      int p = ai;
      if (lane == 0) sIpiv[s][k] = p;
      if (p != k && lane < 9) {
        double t = D[k*9+lane]; D[k*9+lane] = D[p*9+lane]; D[p*9+lane] = t;
      }
      __syncwarp();
      double pv = D[k*9+k];
      if (fabs(pv) < 1e-30) pv = (pv >= 0.0) ? 1e-30 : -1e-30;
      double ipv = drecip(pv);
      if (lane == 0) sDinv[s][k] = ipv;
      if (lane > k && lane < 9) {
        double l = D[lane*9+k] * ipv;
        D[lane*9+k] = l;
        for (int j=k+1;j<9;j++) D[lane*9+j] -= l * D[k*9+j];
      }
      __syncwarp();
    }

    if (lane == 0) {
      int idx[9];
      #pragma unroll
      for (int i=0;i<9;i++) idx[i]=i;
      for (int k=0;k<9;k++){ int p=sIpiv[s][k]; int t=idx[k]; idx[k]=idx[p]; idx[p]=t; }
      #pragma unroll
      for (int i=0;i<9;i++) sPerm[s][i]=idx[i];
    }
    __syncwarp();

    double row[9]; double dinv_l = 1.0; int permL = 0;
    if (lane < 9) {
      #pragma unroll
      for (int j=0;j<9;j++) row[j] = D[lane*9+j];
      dinv_l = sDinv[s][lane];
      permL = sPerm[s][lane];
    }

    double rv = 1.0;
    for (int it=0; it<2; it++) {
      if (lane < 9) sxd[s][lane] = rv;
      __syncwarp();
      if (lane < 9) rv = sxd[s][permL];
      __syncwarp();
      #pragma unroll
      for (int j=0;j<8;j++) {
        double yj = __shfl_sync(FULLM, rv, j);
        if (lane > j && lane < 9) rv -= row[j]*yj;
      }
      #pragma unroll
      for (int j=8;j>=0;j--) {
        if (lane == j) rv *= dinv_l;
        double xj = __shfl_sync(FULLM, rv, j);
        if (lane < j) rv -= row[j]*xj;
      }
      double c2 = (lane < 9) ? rv*rv : 0.0;
      #pragma unroll
      for (int off=16; off; off>>=1) c2 += __shfl_xor_sync(FULLM, c2, off);
      rv *= drsqrt(c2);
    }
    if (lane < 9) sxd[s][lane] = rv;
    __syncwarp();

    if (lane == 0) {
      float e[9];
      #pragma unroll
      for (int k=0;k<9;k++) e[k] = (float)sxd[s][k];

      float G3[3][3];
      #pragma unroll
      for (int i=0;i<3;i++)
        #pragma unroll
        for (int j=0;j<3;j++)
          G3[i][j] = e[0+i]*e[0+j] + e[3+i]*e[3+j] + e[6+i]*e[6+j];

      float Qm[3][3] = {{1.f,0.f,0.f},{0.f,1.f,0.f},{0.f,0.f,1.f}};
      #pragma unroll
      for (int sw=0; sw<4; sw++) { rot3f<0,1>(G3,Qm); rot3f<0,2>(G3,Qm); rot3f<1,2>(G3,Qm); }

      float lam0=G3[0][0], lam1=G3[1][1], lam2=G3[2][2];
      int o0, o1, o2;
      if (lam0 >= lam1) {
        if (lam0 >= lam2) { o0=0; if (lam1>=lam2){o1=1;o2=2;} else {o1=2;o2=1;} }
        else              { o0=2; o1=0; o2=1; }
      } else {
        if (lam1 >= lam2) { o0=1; if (lam0>=lam2){o1=0;o2=2;} else {o1=2;o2=0;} }
        else              { o0=2; o1=1; o2=0; }
      }
      float v1[3] = {Qm[0][o0], Qm[1][o0], Qm[2][o0]};
      float v2[3] = {Qm[0][o1], Qm[1][o1], Qm[2][o1]};
      float v3[3] = {Qm[0][o2], Qm[1][o2], Qm[2][o2]};

      float u1[3], u2[3], u3[3];
      #pragma unroll
      for (int i=0;i<3;i++) {
        u1[i] = e[3*i+0]*v1[0] + e[3*i+1]*v1[1] + e[3*i+2]*v1[2];
        u2[i] = e[3*i+0]*v2[0] + e[3*i+1]*v2[1] + e[3*i+2]*v2[2];
      }
      float in1 = rsqrtf(fmaxf(u1[0]*u1[0]+u1[1]*u1[1]+u1[2]*u1[2], 1e-30f));
      float in2 = rsqrtf(fmaxf(u2[0]*u2[0]+u2[1]*u2[1]+u2[2]*u2[2], 1e-30f));
      #pragma unroll
      for (int i=0;i<3;i++){ u1[i]*=in1; u2[i]*=in2; }
      u3[0] = u1[1]*u2[2] - u1[2]*u2[1];
      u3[1] = u1[2]*u2[0] - u1[0]*u2[2];
      u3[2] = u1[0]*u2[1] - u1[1]*u2[0];
      float in3 = rsqrtf(fmaxf(u3[0]*u3[0]+u3[1]*u3[1]+u3[2]*u3[2], 1e-30f));
      #pragma unroll
      for (int i=0;i<3;i++) u3[i]*=in3;

      float detU = u1[0]*(u2[1]*u3[2]-u2[2]*u3[1])
                 - u1[1]*(u2[0]*u3[2]-u2[2]*u3[0])
                 + u1[2]*(u2[0]*u3[1]-u2[1]*u3[0]);
      float detV = v1[0]*(v2[1]*v3[2]-v2[2]*v3[1])
                 - v1[1]*(v2[0]*v3[2]-v2[2]*v3[0])
                 + v1[2]*(v2[0]*v3[1]-v2[1]*v3[0]);
      float dd = detU * detV;
      sSgnF[s] = (dd > 0.0f) ? 1.0f : ((dd < 0.0f) ? -1.0f : 0.0f);
      #pragma unroll
      for (int i=0;i<3;i++) {
        sUVf[s][i]    = u1[i];
        sUVf[s][3+i]  = u2[i];
        sUVf[s][6+i]  = u3[i];
        sUVf[s][9+i]  = v1[i];
        sUVf[s][12+i] = v2[i];
        sUVf[s][15+i] = v3[i];
        st3[s][i] = u3[i];
      }
    }
    __syncwarp();

    if (lane < 9) {
      int i = lane / 3, j = lane % 3;
      float u1i = sUVf[s][i], u2i = sUVf[s][3+i], u3i = sUVf[s][6+i];
      float v1j = sUVf[s][9+j], v2j = sUVf[s][12+j], v3j = sUVf[s][15+j];
      sR1[s][lane] = ( u2i*v1j - u1i*v2j + u3i*v3j)*sSgnF[s];
    }
  }
  __syncthreads();

  // ---- phase 3: cheirality per batch (smem-staged; H-trick for candidate 2) ----
  for (int s = 0; s < 2; s++) {
    const int bb = blockIdx.x*2 + s;
    float R1[9];
    #pragma unroll
    for (int i=0;i<9;i++) R1[i]=sR1[s][i];
    const float tv0=st3[s][0], tv1=st3[s][1], tv2=st3[s][2];
    float4* sP = s ? sPv1 : sPv0;
    float*  sW = s ? sWv1 : sWv0;

    float sc0=0.f, sc1=0.f, sc2=0.f, sc3=0.f;
    if (sAffine[s]) {
      #pragma unroll
      for (int k = 0; k < NPTS/256; k++) {
        int n = tid + k*256;
        float4 q = sP[n];
        float w = sW[n];
        float bbv = q.z*q.z + q.w*q.w + 1.0f;
        float bt = q.z*tv0 + q.w*tv1 + tv2;
        float a0 = R1[0]*q.x + R1[1]*q.y + R1[2];
        float a1 = R1[3]*q.x + R1[4]*q.y + R1[5];
        float a2 = R1[6]*q.x + R1[7]*q.y + R1[8];
        float aa = a0*a0 + a1*a1 + a2*a2;
        float ab = a0*q.z + a1*q.w + a2;
        float at = a0*tv0 + a1*tv1 + a2*tv2;
        {
          float det = aa*bbv - ab*ab + 1e-9f;
          float n0 = -at*bbv + ab*bt;
          float n1 = aa*bt - ab*at;
          bool dpn = det >= 0.f;
          if (dpn ? (n0 > 0.f && n1 > 0.f) : (n0 < 0.f && n1 < 0.f)) sc0 += w;
          if (dpn ? (n0 < 0.f && n1 < 0.f) : (n0 > 0.f && n1 > 0.f)) sc1 += w;
        }
        {
          float ab2 = 2.0f*at*bt - ab;
          float det = aa*bbv - ab2*ab2 + 1e-9f;
          float n0 = -at*bbv + ab2*bt;
          float n1 = aa*bt - ab2*at;
          bool dpn = det >= 0.f;
          if (dpn ? (n0 > 0.f && n1 > 0.f) : (n0 < 0.f && n1 < 0.f)) sc2 += w;
          if (dpn ? (n0 < 0.f && n1 < 0.f) : (n0 > 0.f && n1 > 0.f)) sc3 += w;
        }
      }
    } else {
      const float2* kp0 = (const float2*)(kpts0) + (size_t)bb*NPTS;
      const float2* kp1 = (const float2*)(kpts1) + (size_t)bb*NPTS;
      const float*  wv  = conf + (size_t)bb*NPTS;
      float Ki0[9], Ki1[9];
      #pragma unroll
      for (int i=0;i<9;i++){ Ki0[i]=sKi[s][i]; Ki1[i]=sKi[s][9+i]; }
      #pragma unroll
      for (int k = 0; k < NPTS/256; k++) {
        int n = tid + k*256;
        float2 p0 = kp0[n]; float2 p1 = kp1[n]; float w = wv[n];
        float x00 = Ki0[0]*p0.x + Ki0[1]*p0.y + Ki0[2];
        float x01 = Ki0[3]*p0.x + Ki0[4]*p0.y + Ki0[5];
        float x02 = Ki0[6]*p0.x + Ki0[7]*p0.y + Ki0[8];
        float x10 = Ki1[0]*p1.x + Ki1[1]*p1.y + Ki1[2];
        float x11 = Ki1[3]*p1.x + Ki1[4]*p1.y + Ki1[5];
        float x12 = Ki1[6]*p1.x + Ki1[7]*p1.y + Ki1[8];
        float bbv = x10*x10 + x11*x11 + x12*x12;
        float bt = x10*tv0 + x11*tv1 + x12*tv2;
        float a0 = R1[0]*x00 + R1[1]*x01 + R1[2]*x02;
        float a1 = R1[3]*x00 + R1[4]*x01 + R1[5]*x02;
        float a2 = R1[6]*x00 + R1[7]*x01 + R1[8]*x02;
        float aa = a0*a0 + a1*a1 + a2*a2;
        float ab = a0*x10 + a1*x11 + a2*x12;
        float at = a0*tv0 + a1*tv1 + a2*tv2;
        {
          float det = aa*bbv - ab*ab + 1e-9f;
          float n0 = -at*bbv + ab*bt;
          float n1 = aa*bt - ab*at;
          bool dpn = det >= 0.f;
          if (dpn ? (n0 > 0.f && n1 > 0.f) : (n0 < 0.f && n1 < 0.f)) sc0 += w;
          if (dpn ? (n0 < 0.f && n1 < 0.f) : (n0 > 0.f && n1 > 0.f)) sc1 += w;
        }
        {
          float ab2 = 2.0f*at*bt - ab;
          float det = aa*bbv - ab2*ab2 + 1e-9f;
          float n0 = -at*bbv + ab2*bt;
          float n1 = aa*bt - ab2*at;
          bool dpn = det >= 0.f;
          if (dpn ? (n0 > 0.f && n1 > 0.f) : (n0 < 0.f && n1 < 0.f)) sc2 += w;
          if (dpn ? (n0 < 0.f && n1 < 0.f) : (n0 > 0.f && n1 > 0.f)) sc3 += w;
        }
      }
    }
    #pragma unroll
    for (int off=16; off; off>>=1) {
      sc0 += __shfl_down_sync(FULLM, sc0, off);
      sc1 += __shfl_down_sync(FULLM, sc1, off);
      sc2 += __shfl_down_sync(FULLM, sc2, off);
      sc3 += __shfl_down_sync(FULLM, sc3, off);
    }
    if (lane == 0) { sred[warp][0]=sc0; sred[warp][1]=sc1; sred[warp][2]=sc2; sred[warp][3]=sc3; }
    __syncthreads();
    if (tid == 0) {
      float s0=0.f, s1=0.f, s2=0.f, s3=0.f;
      #pragma unroll
      for (int wp=0; wp<8; wp++){ s0+=sred[wp][0]; s1+=sred[wp][1]; s2+=sred[wp][2]; s3+=sred[wp][3]; }
      float bs = s0; int bi = 0;
      if (s1 > bs){ bs=s1; bi=1; }
      if (s2 > bs){ bs=s2; bi=2; }
      if (s3 > bs){ bs=s3; bi=3; }
      float Rsel[9];
      if (bi < 2) {
        #pragma unroll
        for (int i=0;i<9;i++) Rsel[i] = sR1[s][i];
      } else {
        float t3a[3] = {st3[s][0], st3[s][1], st3[s][2]};
        #pragma unroll
        for (int i=0;i<3;i++) {
          #pragma unroll
          for (int j=0;j<3;j++) {
            float dotc = t3a[0]*sR1[s][0*3+j] + t3a[1]*sR1[s][1*3+j] + t3a[2]*sR1[s][2*3+j];
            Rsel[i*3+j] = 2.0f*t3a[i]*dotc - sR1[s][i*3+j];
          }
        }
      }
      float sgn = (bi & 1) ? -1.f : 1.f;
      float ts = tscale[bb*2];
      float t0 = (sgn*st3[s][0])*ts;
      float t1 = (sgn*st3[s][1])*ts;
      float t2 = (sgn*st3[s][2])*ts;
      float* o = out + (size_t)bb*32;
      o[0]=Rsel[0]; o[1]=Rsel[1]; o[2]=Rsel[2];  o[3]=t0;
      o[4]=Rsel[3]; o[5]=Rsel[4]; o[6]=Rsel[5];  o[7]=t1;
      o[8]=Rsel[6]; o[9]=Rsel[7]; o[10]=Rsel[8]; o[11]=t2;
      o[12]=0.f; o[13]=0.f; o[14]=0.f; o[15]=1.f;
      float ti0 = -(Rsel[0]*t0 + Rsel[3]*t1 + Rsel[6]*t2);
      float ti1 = -(Rsel[1]*t0 + Rsel[4]*t1 + Rsel[7]*t2);
      float ti2 = -(Rsel[2]*t0 + Rsel[5]*t1 + Rsel[8]*t2);
      o[16]=Rsel[0]; o[17]=Rsel[3]; o[18]=Rsel[6]; o[19]=ti0;
      o[20]=Rsel[1]; o[21]=Rsel[4]; o[22]=Rsel[7]; o[23]=ti1;
      o[24]=Rsel[2]; o[25]=Rsel[5]; o[26]=Rsel[8]; o[27]=ti2;
      o[28]=0.f; o[29]=0.f; o[30]=0.f; o[31]=1.f;
    }
    __syncthreads();
  }
}

extern "C" void kernel_launch(void* const* d_in, const int* in_sizes, int n_in,
                              void* d_out, int out_size) {
  const float* kpts0  = (const float*)d_in[0];
  const float* kpts1  = (const float*)d_in[1];
  const float* conf   = (const float*)d_in[2];
  const float* tscale = (const float*)d_in[3];
  const float* Kmat   = (const float*)d_in[4];
  float* out = (float*)d_out;

  cudaFuncSetAttribute(k_fused, cudaFuncAttributeMaxDynamicSharedMemorySize, DYN_SMEM);
  k_fused<<<BATCH/2, 256, DYN_SMEM>>>(kpts0, kpts1, conf, tscale, Kmat, out);
}